// round 14
// baseline (speedup 1.0000x reference)
#include <cuda_runtime.h>
#include <math.h>

// Problem dims
#define Bn  128
#define Ln  256
#define Hn  512
#define HW  256            // Hn/2 packed words
#define H3n 1536
#define On  256
#define BLn (Bn * Ln)
#define NBLK 128
#define GRP  32

// Recurrence smem (uint32 words): Whz2 [256][40], Whh2 [256][24], Ahs2 [32][260]
#define WZS 40
#define WHS 24
#define APR 260
#define WHZ_W (256 * WZS)
#define WHH_W (256 * WHS)
#define AHS_W (32 * APR)
#define REC_SMEM_BYTES ((WHZ_W + WHH_W + AHS_W) * 4)   // ~98.8 KB

// k_mma 3-stage dynamic smem: per buffer A 128x16, W 128x16 floats
#define MMA_AS_F 2048
#define MMA_WS_F 2048
#define MMA_SMEM_BYTES (3 * (MMA_AS_F + MMA_WS_F) * 4)   // 49152 B

// -------------------- scratch -----------------------------------------------
__device__ float g_xhat  [(size_t)BLn * Hn];   // tf32-rounded, K-permuted
__device__ float g_maskf [(size_t)BLn * Hn];   // 0/1 exact, K-permuted
__device__ float g_delta [(size_t)BLn * Hn];   // tf32-rounded, K-permuted
__device__ float g_gammah[(size_t)BLn * Hn];
__device__ float g_pre   [(size_t)BLn * H3n];
__device__ float g_hseq  [(size_t)BLn * Hn];   // tf32-rounded, K-permuted
__device__ float g_hs    [Bn * Hn];            // fp32 carry (state)
__device__ unsigned g_hsr[Bn * HW];            // bf16x2 shadow (A-operand)
__device__ float g_z     [Bn * Hn];
__device__ unsigned g_rh [Bn * HW];            // bf16x2 r*hs (A-operand)
__device__ unsigned g_flags[4 * 256];          // barrier flag lines, 1KB apart
// tf32-rounded, K-permuted weight copies: layout [(kc*N + n)*16 + p]
__device__ float g_wx  [(size_t)Hn * H3n];
__device__ float g_wm  [(size_t)Hn * H3n];
__device__ float g_wgh [(size_t)Hn * Hn];
__device__ float g_wout[(size_t)Hn * On];

// -------------------- helpers -------------------------------------------------
__device__ __forceinline__ float to_tf32(float x) {
    float y;
    asm("cvt.rna.tf32.f32 %0, %1;" : "=f"(y) : "f"(x));
    return y;
}
__device__ __forceinline__ unsigned pack_bf16(float lo, float hi) {
    unsigned r;
    asm("cvt.rn.bf16x2.f32 %0, %1, %2;" : "=r"(r) : "f"(hi), "f"(lo));
    return r;
}
__device__ __forceinline__ float bf16_lo(unsigned w) { return __uint_as_float(w << 16); }
__device__ __forceinline__ float bf16_hi(unsigned w) { return __uint_as_float(w & 0xffff0000u); }
// within-16 K permutation: p(r) = 4*(r%4) + r/4  (involution inverse: r = 4*(p%4)+p/4)
__device__ __forceinline__ int permH(int h) {
    return (h & ~15) | (((h & 3) << 2) | ((h & 15) >> 2));
}

__device__ __forceinline__ void mma_tf32(float& d0, float& d1, float& d2, float& d3,
                                         unsigned a0, unsigned a1, unsigned a2, unsigned a3,
                                         unsigned b0, unsigned b1)
{
    asm volatile(
        "mma.sync.aligned.m16n8k8.row.col.f32.tf32.tf32.f32 "
        "{%0,%1,%2,%3}, {%4,%5,%6,%7}, {%8,%9}, {%0,%1,%2,%3};"
        : "+f"(d0), "+f"(d1), "+f"(d2), "+f"(d3)
        : "r"(a0), "r"(a1), "r"(a2), "r"(a3), "r"(b0), "r"(b1));
}
__device__ __forceinline__ void mma_bf16(float& d0, float& d1, float& d2, float& d3,
                                         unsigned a0, unsigned a1, unsigned a2, unsigned a3,
                                         unsigned b0, unsigned b1)
{
    asm volatile(
        "mma.sync.aligned.m16n8k16.row.col.f32.bf16.bf16.f32 "
        "{%0,%1,%2,%3}, {%4,%5,%6,%7}, {%8,%9}, {%0,%1,%2,%3};"
        : "+f"(d0), "+f"(d1), "+f"(d2), "+f"(d3)
        : "r"(a0), "r"(a1), "r"(a2), "r"(a3), "r"(b0), "r"(b1));
}

__device__ __forceinline__ void cp_async16(void* smem, const void* gmem) {
    unsigned s = (unsigned)__cvta_generic_to_shared(smem);
    asm volatile("cp.async.cg.shared.global [%0], [%1], 16;" :: "r"(s), "l"(gmem));
}
__device__ __forceinline__ void cp_commit() {
    asm volatile("cp.async.commit_group;");
}
template <int N>
__device__ __forceinline__ void cp_wait() {
    asm volatile("cp.async.wait_group %0;" :: "n"(N));
}

// -------------------- init ---------------------------------------------------
__global__ void k_init_hs() {
    int i = blockIdx.x * blockDim.x + threadIdx.x;
    if (i < Bn * Hn) g_hs[i] = 0.f;
    if (i < Bn * HW) g_hsr[i] = 0u;
    if (i < 4 * 256) g_flags[i] = 0u;
}

// -------------------- fused weight tf32 pre-round + K-permute ----------------
#define N1 (Hn * H3n)
#define N3 (Hn * Hn)
#define N4 (Hn * On)
__global__ void k_cvt_all(const float* __restrict__ Wx, const float* __restrict__ Wm,
                          const float* __restrict__ Wgh, const float* __restrict__ Wout)
{
    int i = blockIdx.x * blockDim.x + threadIdx.x;
    const float* src; float* dst; int N; int rel;
    if (i < N1)                    { src = Wx;   dst = g_wx;   N = H3n; rel = i; }
    else if (i < 2 * N1)           { src = Wm;   dst = g_wm;   N = H3n; rel = i - N1; }
    else if (i < 2 * N1 + N3)      { src = Wgh;  dst = g_wgh;  N = Hn;  rel = i - 2 * N1; }
    else if (i < 2 * N1 + N3 + N4) { src = Wout; dst = g_wout; N = On;  rel = i - 2 * N1 - N3; }
    else return;
    int p  = rel & 15;
    int n  = (rel >> 4) % N;
    int kc = rel / (16 * N);
    int k  = kc * 16 + 4 * (p & 3) + (p >> 2);
    dst[rel] = to_tf32(src[(size_t)k * N + n]);
}

// -------------------- prep (writes K-permuted A matrices) --------------------
__global__ void k_prep(const float* __restrict__ C, const float* __restrict__ t,
                       const int* __restrict__ mask,
                       const float* __restrict__ w_gx, const float* __restrict__ b_gx)
{
    int idx = blockIdx.x * blockDim.x + threadIdx.x;
    int b = idx >> 9;
    int h = idx & (Hn - 1);
    const int* mrow = mask + (size_t)b * Ln * Hn + h;
    const int hp = permH(h);

    float num = 0.f, cnt = 0.f;
    for (int l = 0; l < Ln; ++l) {
        float mi = (float)mrow[(size_t)l * Hn];
        float x  = C[l * Hn + h];
        num += mi * x;
        cnt += mi;
    }
    float xmean = num / fmaxf(cnt, 1.f);

    float d_prev = 0.f, m_prev = 1.f, x_last = xmean;
    float wg = w_gx[h], bg = b_gx[h];
    float tprev = t[b * Ln];
    for (int l = 0; l < Ln; ++l) {
        float tcur = t[b * Ln + l];
        float dtv  = tcur - tprev;
        tprev = tcur;
        float delta = dtv + (1.f - m_prev) * d_prev;
        float gx = expf(-fmaxf(wg * delta + bg, 0.f));
        float mi = (float)mrow[(size_t)l * Hn];
        float x  = C[l * Hn + h];
        float xh = mi * x + (1.f - mi) * (gx * x_last + (1.f - gx) * xmean);
        size_t o = ((size_t)b * Ln + l) * Hn + hp;
        g_delta[o] = to_tf32(delta);
        g_xhat[o]  = to_tf32(xh);
        g_maskf[o] = mi;
        x_last = mi * x + (1.f - mi) * x_last;
        d_prev = delta;
        m_prev = mi;
    }
}

// -------------------- tf32 GEMM, 3-stage cp.async, vectorized LDS.128 --------
// A [M][K] K-permuted per 16-block; W [(kc*N+n)*16+p]. Frags load as float4.
template <int ACT>
__global__ __launch_bounds__(256)
void k_mma(const float* __restrict__ A, const float* __restrict__ A2,
           const float* __restrict__ W, const float* __restrict__ W2,
           const float* __restrict__ bias, float* __restrict__ Cout,
           int M, int N, int K)
{
    extern __shared__ float dsm[];

    const int tid  = threadIdx.x;
    const int bm   = blockIdx.y * 128;
    const int bn   = blockIdx.x * 128;
    const int wid  = tid >> 5, lane = tid & 31;
    const int wm   = (wid >> 1) * 32;
    const int wn   = (wid & 1) * 64;
    const int g    = lane >> 2;
    const int tg   = lane & 3;

    float d[2][8][4] = {};

    const int cpp = K >> 4;
    const int nch = (A2 ? 2 : 1) * cpp;

    auto stage = [&](int c, int buf) {
        const float* Ap = (c >= cpp) ? A2 : A;
        const float* Wp = (c >= cpp) ? W2 : W;
        const int kc = (c >= cpp ? c - cpp : c);
        float* As = dsm + buf * MMA_AS_F;
        float* Ws = dsm + 3 * MMA_AS_F + buf * MMA_WS_F;
        #pragma unroll
        for (int it = 0; it < 2; ++it) {
            int idx = tid + it * 256;          // 0..511
            int r = idx >> 2, q = (idx & 3) << 2;
            cp_async16(&As[r * 16 + q], Ap + (size_t)(bm + r) * K + kc * 16 + q);
            cp_async16(&Ws[r * 16 + q], Wp + ((size_t)kc * N + bn + r) * 16 + q);
        }
        cp_commit();
    };

    stage(0, 0);
    stage(1, 1);

    for (int c = 0; c < nch; ++c) {
        if (c + 1 < nch) cp_wait<1>();
        else             cp_wait<0>();
        __syncthreads();
        if (c + 2 < nch) stage(c + 2, (c + 2) % 3);

        const float* As = dsm + (c % 3) * MMA_AS_F;
        const float* Ws = dsm + 3 * MMA_AS_F + (c % 3) * MMA_WS_F;

        float4 a0[2], a8[2];
        #pragma unroll
        for (int mt = 0; mt < 2; ++mt) {
            int r = wm + mt * 16 + g;
            a0[mt] = *(const float4*)&As[r * 16 + tg * 4];
            a8[mt] = *(const float4*)&As[(r + 8) * 16 + tg * 4];
        }
        #pragma unroll
        for (int nt = 0; nt < 8; ++nt) {
            float4 wb = *(const float4*)&Ws[(wn + nt * 8 + g) * 16 + tg * 4];
            unsigned b0 = __float_as_uint(wb.x), b1 = __float_as_uint(wb.y);
            unsigned b2 = __float_as_uint(wb.z), b3 = __float_as_uint(wb.w);
            #pragma unroll
            for (int mt = 0; mt < 2; ++mt) {
                mma_tf32(d[mt][nt][0], d[mt][nt][1], d[mt][nt][2], d[mt][nt][3],
                         __float_as_uint(a0[mt].x), __float_as_uint(a8[mt].x),
                         __float_as_uint(a0[mt].y), __float_as_uint(a8[mt].y),
                         b0, b1);
                mma_tf32(d[mt][nt][0], d[mt][nt][1], d[mt][nt][2], d[mt][nt][3],
                         __float_as_uint(a0[mt].z), __float_as_uint(a8[mt].z),
                         __float_as_uint(a0[mt].w), __float_as_uint(a8[mt].w),
                         b2, b3);
            }
        }
    }

    #pragma unroll
    for (int mt = 0; mt < 2; ++mt) {
        int r0 = bm + wm + mt * 16 + g;
        #pragma unroll
        for (int nt = 0; nt < 8; ++nt) {
            int col = bn + wn + nt * 8 + 2 * tg;
            float2 bv = *(const float2*)&bias[col];
            float v0 = d[mt][nt][0] + bv.x;
            float v1 = d[mt][nt][1] + bv.y;
            float v2 = d[mt][nt][2] + bv.x;
            float v3 = d[mt][nt][3] + bv.y;
            if (ACT == 1) {
                v0 = expf(-fmaxf(v0, 0.f)); v1 = expf(-fmaxf(v1, 0.f));
                v2 = expf(-fmaxf(v2, 0.f)); v3 = expf(-fmaxf(v3, 0.f));
            }
            float2 o0 = {v0, v1}, o1 = {v2, v3};
            *(float2*)&Cout[(size_t)r0 * N + col] = o0;
            *(float2*)&Cout[(size_t)(r0 + 8) * N + col] = o1;
        }
    }
}

// -------------------- persistent recurrence: bf16 m16n8k16 -------------------
__global__ __launch_bounds__(256)
void k_recurrence(const float* __restrict__ Wh)
{
    extern __shared__ unsigned smw[];
    unsigned* Whz2 = smw;
    unsigned* Whh2 = Whz2 + WHZ_W;
    unsigned* Ahs2 = Whh2 + WHH_W;

    const int tid  = threadIdx.x;
    const int wid  = tid >> 5, lane = tid & 31;
    const int g    = lane >> 2, tg = lane & 3;
    const int bt   = blockIdx.x & 3;
    const int m0   = bt * 32;
    const int nt   = blockIdx.x >> 2;
    const int n0p0 = nt * 32;
    const int n0p1 = nt * 16;

    const int wm0 = (wid >> 2) * 16;
    const int wn0 = (wid & 3) * 8;
    const int wm1 = (wid >> 1) * 16;
    const int wn1 = (wid & 1) * 8;

    // ---- stage weights (bf16x2 packed along K) once ----
    for (int idx = tid; idx < 256 * 32; idx += 256) {
        int kp = idx >> 5, j = idx & 31;
        float lo = Wh[(size_t)(2 * kp) * H3n + n0p0 + j];
        float hi = Wh[(size_t)(2 * kp + 1) * H3n + n0p0 + j];
        Whz2[kp * WZS + j] = pack_bf16(lo, hi);
    }
    for (int idx = tid; idx < 256 * 16; idx += 256) {
        int kp = idx >> 4, j = idx & 15;
        float lo = Wh[(size_t)(2 * kp) * H3n + 1024 + n0p1 + j];
        float hi = Wh[(size_t)(2 * kp + 1) * H3n + 1024 + n0p1 + j];
        Whh2[kp * WHS + j] = pack_bf16(lo, hi);
    }
    __syncthreads();

    const bool isz = (n0p0 < Hn);
    const int c0  = n0p0 + wn0 + 2 * tg;
    const int jj1 = n0p1 + wn1 + 2 * tg;

    unsigned cnt = 0;
    unsigned* flags = &g_flags[bt * 256];

    auto bar_arrive = [&]() {
        // callers do __syncthreads() first
        ++cnt;
        if (tid == 0)
            asm volatile("st.release.gpu.global.u32 [%0], %1;"
                         :: "l"(&flags[nt]), "r"(cnt) : "memory");
    };
    auto bar_wait_ = [&]() {
        if (wid == 0) {
            const unsigned* fp = &flags[lane];
            unsigned v;
            do {
                asm volatile("ld.acquire.gpu.global.u32 %0, [%1];"
                             : "=r"(v) : "l"(fp) : "memory");
            } while (__any_sync(0xffffffffu, v < cnt));
        }
        __syncthreads();
    };

    auto stage_half = [&](const unsigned* src, int kh) {
        #pragma unroll
        for (int it = 0; it < 4; ++it) {
            int idx = tid + it * 256;
            int m  = idx >> 5;
            int kp = kh + ((idx & 31) << 2);
            cp_async16(&Ahs2[m * APR + kp], src + (m0 + m) * HW + kp);
        }
        cp_commit();
    };

    float2 p0[2];
    #pragma unroll
    for (int i = 0; i < 2; ++i) {
        size_t row = (size_t)(m0 + wm0 + g + 8 * i) * Ln + 0;
        p0[i] = *(const float2*)&g_pre[row * H3n + c0];
    }

    for (int t = 0; t < Ln; ++t) {
        stage_half(g_hsr, 0);
        stage_half(g_hsr, 128);
        cp_wait<1>();
        __syncthreads();

        // ============ phase 0: mma 32x32x512 bf16, K-split ============
        float d0 = 0.f, d1 = 0.f, d2 = 0.f, d3 = 0.f;
        {
            const unsigned* ar0 = &Ahs2[(wm0 + g) * APR];
            const unsigned* ar1 = &Ahs2[(wm0 + g + 8) * APR];
            #pragma unroll 8
            for (int kb = 0; kb < 128; kb += 8) {
                unsigned a0 = ar0[kb + tg];
                unsigned a1 = ar1[kb + tg];
                unsigned a2 = ar0[kb + tg + 4];
                unsigned a3 = ar1[kb + tg + 4];
                unsigned b0 = Whz2[(kb + tg) * WZS + wn0 + g];
                unsigned b1 = Whz2[(kb + tg + 4) * WZS + wn0 + g];
                mma_bf16(d0, d1, d2, d3, a0, a1, a2, a3, b0, b1);
            }
            cp_wait<0>();
            __syncthreads();
            #pragma unroll 8
            for (int kb = 128; kb < 256; kb += 8) {
                unsigned a0 = ar0[kb + tg];
                unsigned a1 = ar1[kb + tg];
                unsigned a2 = ar0[kb + tg + 4];
                unsigned a3 = ar1[kb + tg + 4];
                unsigned b0 = Whz2[(kb + tg) * WZS + wn0 + g];
                unsigned b1 = Whz2[(kb + tg + 4) * WZS + wn0 + g];
                mma_bf16(d0, d1, d2, d3, a0, a1, a2, a3, b0, b1);
            }
        }
        {
            float dd[2][2] = {{d0, d1}, {d2, d3}};
            #pragma unroll
            for (int i = 0; i < 2; ++i) {
                int rowL = wm0 + g + 8 * i;
                int bb   = m0 + rowL;
                float v0 = p0[i].x + dd[i][0];
                float v1 = p0[i].y + dd[i][1];
                float s0 = 1.f / (1.f + expf(-v0));
                float s1 = 1.f / (1.f + expf(-v1));
                if (isz) {
                    float2 o = {s0, s1};
                    *(float2*)&g_z[bb * Hn + c0] = o;
                } else {
                    int hw = (c0 - Hn) >> 1;
                    unsigned hsw = Ahs2[rowL * APR + hw];
                    g_rh[bb * HW + hw] = pack_bf16(s0 * bf16_lo(hsw),
                                                   s1 * bf16_hi(hsw));
                }
            }
        }

        // ---- barrier A: arrive early, prefetch independents, wait late ----
        __syncthreads();
        bar_arrive();
        float2 p1[2], ga[2], hv[2];
        if (wid < 4) {
            #pragma unroll
            for (int i = 0; i < 2; ++i) {
                int bb = m0 + wm1 + g + 8 * i;
                size_t row = (size_t)bb * Ln + t;
                p1[i] = *(const float2*)&g_pre[row * H3n + 1024 + jj1];
                if (t + 1 < Ln) ga[i] = *(const float2*)&g_gammah[(row + 1) * Hn + jj1];
                else            { ga[i].x = 0.f; ga[i].y = 0.f; }
                hv[i] = *(const float2*)&g_hs[bb * Hn + jj1];
            }
        }
        bar_wait_();

        // ---- stage A = rh tile; z loads overlap ----
        stage_half(g_rh, 0);
        stage_half(g_rh, 128);
        float2 zv[2];
        if (wid < 4) {
            #pragma unroll
            for (int i = 0; i < 2; ++i) {
                int bb = m0 + wm1 + g + 8 * i;
                zv[i] = __ldcg((const float2*)&g_z[bb * Hn + jj1]);
            }
        }
        cp_wait<1>();
        __syncthreads();

        // ============ phase 1: mma 32x16x512 bf16 (warps 0-3), K-split ============
        float e0 = 0.f, e1 = 0.f, e2 = 0.f, e3 = 0.f;
        if (wid < 4) {
            const unsigned* ar0 = &Ahs2[(wm1 + g) * APR];
            const unsigned* ar1 = &Ahs2[(wm1 + g + 8) * APR];
            #pragma unroll 8
            for (int kb = 0; kb < 128; kb += 8) {
                unsigned a0 = ar0[kb + tg];
                unsigned a1 = ar1[kb + tg];
                unsigned a2 = ar0[kb + tg + 4];
                unsigned a3 = ar1[kb + tg + 4];
                unsigned b0 = Whh2[(kb + tg) * WHS + wn1 + g];
                unsigned b1 = Whh2[(kb + tg + 4) * WHS + wn1 + g];
                mma_bf16(e0, e1, e2, e3, a0, a1, a2, a3, b0, b1);
            }
        }
        cp_wait<0>();
        __syncthreads();
        if (wid < 4) {
            const unsigned* ar0 = &Ahs2[(wm1 + g) * APR];
            const unsigned* ar1 = &Ahs2[(wm1 + g + 8) * APR];
            #pragma unroll 8
            for (int kb = 128; kb < 256; kb += 8) {
                unsigned a0 = ar0[kb + tg];
                unsigned a1 = ar1[kb + tg];
                unsigned a2 = ar0[kb + tg + 4];
                unsigned a3 = ar1[kb + tg + 4];
                unsigned b0 = Whh2[(kb + tg) * WHS + wn1 + g];
                unsigned b1 = Whh2[(kb + tg + 4) * WHS + wn1 + g];
                mma_bf16(e0, e1, e2, e3, a0, a1, a2, a3, b0, b1);
            }
            float dd[2][2] = {{e0, e1}, {e2, e3}};
            #pragma unroll
            for (int i = 0; i < 2; ++i) {
                int bb = m0 + wm1 + g + 8 * i;
                size_t row = (size_t)bb * Ln + t;
                float v0 = p1[i].x + dd[i][0];
                float v1 = p1[i].y + dd[i][1];
                float h0 = tanhf(v0);
                float h1 = tanhf(v1);
                float hn0 = (1.f - zv[i].x) * hv[i].x + zv[i].x * h0;
                float hn1 = (1.f - zv[i].y) * hv[i].y + zv[i].y * h1;
                // K-permuted hseq for the out-GEMM
                g_hseq[row * Hn + permH(jj1)]     = to_tf32(hn0);
                g_hseq[row * Hn + permH(jj1 + 1)] = to_tf32(hn1);
                float c0v = ga[i].x * hn0;
                float c1v = ga[i].y * hn1;
                float2 carry = {c0v, c1v};
                *(float2*)&g_hs[bb * Hn + jj1] = carry;
                g_hsr[bb * HW + (jj1 >> 1)] = pack_bf16(c0v, c1v);
            }
        }

        // ---- barrier B: arrive early, prefetch next-step p0, wait late ----
        __syncthreads();
        bar_arrive();
        if (t + 1 < Ln) {
            #pragma unroll
            for (int i = 0; i < 2; ++i) {
                size_t row = (size_t)(m0 + wm0 + g + 8 * i) * Ln + (t + 1);
                p0[i] = *(const float2*)&g_pre[row * H3n + c0];
            }
        }
        bar_wait_();
    }
}

// -------------------- launch -------------------------------------------------
extern "C" void kernel_launch(void* const* d_in, const int* in_sizes, int n_in,
                              void* d_out, int out_size)
{
    (void)in_sizes; (void)n_in; (void)out_size;
    const float* C     = (const float*)d_in[0];
    const float* t     = (const float*)d_in[1];
    const int*   mask  = (const int*)  d_in[2];
    const float* Wx    = (const float*)d_in[3];
    const float* Wh    = (const float*)d_in[4];
    const float* Wm    = (const float*)d_in[5];
    const float* bvec  = (const float*)d_in[6];
    const float* w_gx  = (const float*)d_in[7];
    const float* b_gx  = (const float*)d_in[8];
    const float* W_gh  = (const float*)d_in[9];
    const float* b_gh  = (const float*)d_in[10];
    const float* W_out = (const float*)d_in[11];
    const float* b_out = (const float*)d_in[12];
    float* out = (float*)d_out;

    float *p_xhat, *p_maskf, *p_delta, *p_gammah, *p_pre, *p_hseq;
    float *p_wx, *p_wm, *p_wgh, *p_wout;
    cudaGetSymbolAddress((void**)&p_xhat,   g_xhat);
    cudaGetSymbolAddress((void**)&p_maskf,  g_maskf);
    cudaGetSymbolAddress((void**)&p_delta,  g_delta);
    cudaGetSymbolAddress((void**)&p_gammah, g_gammah);
    cudaGetSymbolAddress((void**)&p_pre,    g_pre);
    cudaGetSymbolAddress((void**)&p_hseq,   g_hseq);
    cudaGetSymbolAddress((void**)&p_wx,     g_wx);
    cudaGetSymbolAddress((void**)&p_wm,     g_wm);
    cudaGetSymbolAddress((void**)&p_wgh,    g_wgh);
    cudaGetSymbolAddress((void**)&p_wout,   g_wout);

    cudaFuncSetAttribute(k_recurrence,
                         cudaFuncAttributeMaxDynamicSharedMemorySize,
                         REC_SMEM_BYTES);
    cudaFuncSetAttribute(k_mma<0>,
                         cudaFuncAttributeMaxDynamicSharedMemorySize,
                         MMA_SMEM_BYTES);
    cudaFuncSetAttribute(k_mma<1>,
                         cudaFuncAttributeMaxDynamicSharedMemorySize,
                         MMA_SMEM_BYTES);

    // 1) init + scans + fused weight pre-round/permute
    k_init_hs<<<(Bn * Hn + 255) / 256, 256>>>();
    k_prep<<<(Bn * Hn) / 256, 256>>>(C, t, mask, w_gx, b_gx);
    k_cvt_all<<<(2 * N1 + N3 + N4 + 255) / 256, 256>>>(Wx, Wm, W_gh, W_out);

    // 2) pre = x_hat@Wx + mask@Wm + b
    k_mma<0><<<dim3(H3n / 128, BLn / 128), 256, MMA_SMEM_BYTES>>>(
        p_xhat, p_maskf, p_wx, p_wm, bvec, p_pre, BLn, H3n, Hn);

    // 3) gamma_h = exp(-relu(delta@W_gh + b_gh))
    k_mma<1><<<dim3(Hn / 128, BLn / 128), 256, MMA_SMEM_BYTES>>>(
        p_delta, nullptr, p_wgh, nullptr, b_gh, p_gammah, BLn, Hn, Hn);

    // 4) recurrence: persistent, bf16 tensor-core phases, flag-line barriers
    k_recurrence<<<NBLK, 256, REC_SMEM_BYTES>>>(Wh);

    // 5) out = h_seq @ W_out + b_out
    k_mma<0><<<dim3(On / 128, BLn / 128), 256, MMA_SMEM_BYTES>>>(
        p_hseq, nullptr, p_wout, nullptr, b_out, out, BLn, On, Hn);
}